// round 3
// baseline (speedup 1.0000x reference)
#include <cuda_runtime.h>
#include <cstdint>

// Problem dimensions (fixed by the reference).
#define NW 50000
#define NT 2000
#define ND 50000
#define DO 128

// Degree-array layout: one float counter per (relation, dst-node).
constexpr int DEG_WW = 0;
constexpr int DEG_WT = NW;
constexpr int DEG_TT = NW + NT;
constexpr int DEG_WD = NW + 2 * NT;
constexpr int DEG_TD = NW + 2 * NT + ND;
constexpr int NDEG   = NW + 2 * NT + 2 * ND;   // 154000

// ---------------------------------------------------------------------------
// Scratch (static __device__ arrays — allocation-free per harness rules).
// ---------------------------------------------------------------------------
__device__ float g_Wh_ww[(size_t)NW * DO];
__device__ float g_Wh_wt[(size_t)NW * DO];
__device__ float g_Wh_wd[(size_t)NW * DO];
__device__ float g_Wh_td[(size_t)NT * DO];
__device__ float g_Wh_tt[(size_t)NT * DO];

__device__ float g_s_ww[(size_t)NW * DO];
__device__ float g_s_wt[(size_t)NT * DO];
__device__ float g_s_tt[(size_t)NT * DO];
__device__ float g_s_wd[(size_t)ND * DO];
__device__ float g_s_td[(size_t)ND * DO];

__device__ float g_deg[NDEG];

// rel ids: 0=ww, 1=wt, 2=tt, 3=wd, 4=td
__device__ __forceinline__ float* wh_ptr(int rel) {
    switch (rel) {
        case 0:  return g_Wh_ww;
        case 1:  return g_Wh_wt;
        case 2:  return g_Wh_tt;
        case 3:  return g_Wh_wd;
        default: return g_Wh_td;
    }
}
__device__ __forceinline__ float* s_ptr(int rel) {
    switch (rel) {
        case 0:  return g_s_ww;
        case 1:  return g_s_wt;
        case 2:  return g_s_tt;
        case 3:  return g_s_wd;
        default: return g_s_td;
    }
}
__device__ __forceinline__ int deg_off(int rel) {
    switch (rel) {
        case 0:  return DEG_WW;
        case 1:  return DEG_WT;
        case 2:  return DEG_TT;
        case 3:  return DEG_WD;
        default: return DEG_TD;
    }
}

// ---------------------------------------------------------------------------
// Zero accumulators + degrees.
// ---------------------------------------------------------------------------
__global__ void zero_all() {
    size_t i = (size_t)blockIdx.x * blockDim.x + threadIdx.x;
    if (i < (size_t)NW * DO) g_s_ww[i] = 0.0f;
    if (i < (size_t)NT * DO) { g_s_wt[i] = 0.0f; g_s_tt[i] = 0.0f; }
    if (i < (size_t)ND * DO) { g_s_wd[i] = 0.0f; g_s_td[i] = 0.0f; }
    if (i < (size_t)NDEG)    g_deg[i] = 0.0f;
}

// ---------------------------------------------------------------------------
// Tiled fp32 GEMM + bias: C[M x 128] = A[M x DIN] @ W[DIN x 128] + b
// BM=64, BN=128, BK=32, 256 threads, thread tile 8 rows x 4 cols.
// A-tile reads from shared are warp-broadcast (free); B-tile reads are LDS.128
// with 4-phase conflict-free access.
// ---------------------------------------------------------------------------
template <int DIN>
__global__ __launch_bounds__(256)
void gemm_bias_k(const float* __restrict__ A, const float* __restrict__ W,
                 const float* __restrict__ bias, int rel, int M) {
    constexpr int BM = 64, BN = 128, BK = 32;
    __shared__ float As[BM][BK];
    __shared__ float Bs[BK][BN];

    const int t    = threadIdx.x;
    const int m0   = blockIdx.x * BM;
    const int lane = t & 31;
    const int col  = lane * 4;       // 0..124
    const int row0 = (t >> 5) * 8;   // 0..56

    float acc[8][4] = {};

    for (int k0 = 0; k0 < DIN; k0 += BK) {
        // Load A tile: 64x32 floats, 8 per thread (2x float4).
        {
            int r = t >> 2;            // 0..63
            int c = (t & 3) * 8;       // 0,8,16,24
            float4 v0, v1;
            if (m0 + r < M) {
                const float* src = A + (size_t)(m0 + r) * DIN + k0 + c;
                v0 = *(const float4*)(src);
                v1 = *(const float4*)(src + 4);
            } else {
                v0 = make_float4(0.f, 0.f, 0.f, 0.f);
                v1 = v0;
            }
            *(float4*)&As[r][c]     = v0;
            *(float4*)&As[r][c + 4] = v1;
        }
        // Load B tile: 32x128 floats, 16 per thread (4x float4).
        {
            int rb = t >> 5;  // 0..7
#pragma unroll
            for (int i = 0; i < 4; i++) {
                int r = rb + i * 8;
                *(float4*)&Bs[r][lane * 4] =
                    *(const float4*)(W + (size_t)(k0 + r) * BN + lane * 4);
            }
        }
        __syncthreads();

#pragma unroll
        for (int k = 0; k < BK; k++) {
            float bv[4];
            *(float4*)bv = *(float4*)&Bs[k][col];
#pragma unroll
            for (int r = 0; r < 8; r++) {
                float a = As[row0 + r][k];
                acc[r][0] += a * bv[0];
                acc[r][1] += a * bv[1];
                acc[r][2] += a * bv[2];
                acc[r][3] += a * bv[3];
            }
        }
        __syncthreads();
    }

    float* C = wh_ptr(rel);
    float4 bv = *(const float4*)(bias + col);
#pragma unroll
    for (int r = 0; r < 8; r++) {
        int m = m0 + row0 + r;
        if (m < M) {
            float4 o = make_float4(acc[r][0] + bv.x, acc[r][1] + bv.y,
                                   acc[r][2] + bv.z, acc[r][3] + bv.w);
            *(float4*)(C + (size_t)m * BN + col) = o;
        }
    }
}

// ---------------------------------------------------------------------------
// Edge scatter: one warp per edge. Each lane handles one float4 of the 128-wide
// row. Vector reduction red.global.add.v4.f32 (sm_90+) cuts atomic instruction
// count 4x vs scalar atomicAdd. Lane 0 bumps the degree counter.
// ---------------------------------------------------------------------------
__global__ __launch_bounds__(256)
void scatter_rel(const int* __restrict__ src, const int* __restrict__ dst,
                 const float* __restrict__ w, int rel, int E) {
    int gw   = (int)(((size_t)blockIdx.x * blockDim.x + threadIdx.x) >> 5);
    int lane = threadIdx.x & 31;
    if (gw >= E) return;

    int   sN = src[gw];
    int   dN = dst[gw];
    float ew = w[gw];

    const float* Wh = wh_ptr(rel);
    float*       S  = s_ptr(rel);

    float4 v = *(const float4*)(Wh + (size_t)sN * DO + lane * 4);
    v.x *= ew; v.y *= ew; v.z *= ew; v.w *= ew;

    float* p = S + (size_t)dN * DO + lane * 4;
    asm volatile("red.global.add.v4.f32 [%0], {%1, %2, %3, %4};"
                 :: "l"(p), "f"(v.x), "f"(v.y), "f"(v.z), "f"(v.w)
                 : "memory");

    if (lane == 0) atomicAdd(g_deg + deg_off(rel) + dN, 1.0f);
}

// ---------------------------------------------------------------------------
// Combine: per-destination mean, cross-etype sum, write output
// [h_word(50000x128) | h_topic(2000x128) | h_doc(50000x128)].
// ---------------------------------------------------------------------------
__device__ __forceinline__ float inv_or_zero(float d) {
    return d > 0.0f ? 1.0f / d : 0.0f;
}

__global__ __launch_bounds__(256)
void combine(float* __restrict__ out) {
    constexpr int ROWS = NW + NT + ND;          // 102000
    constexpr int TOT4 = ROWS * (DO / 4);       // float4 elements
    int i = (int)((size_t)blockIdx.x * blockDim.x + threadIdx.x);
    if (i >= TOT4) return;

    int row = i >> 5;           // DO/4 = 32 float4 per row
    int c   = (i & 31) * 4;     // float offset within row

    float4 o;
    if (row < NW) {
        float  inv = inv_or_zero(g_deg[DEG_WW + row]);
        float4 v   = *(const float4*)(g_s_ww + (size_t)row * DO + c);
        o = make_float4(v.x * inv, v.y * inv, v.z * inv, v.w * inv);
    } else if (row < NW + NT) {
        int    r    = row - NW;
        float  inv1 = inv_or_zero(g_deg[DEG_WT + r]);
        float  inv2 = inv_or_zero(g_deg[DEG_TT + r]);
        float4 v1   = *(const float4*)(g_s_wt + (size_t)r * DO + c);
        float4 v2   = *(const float4*)(g_s_tt + (size_t)r * DO + c);
        o = make_float4(v1.x * inv1 + v2.x * inv2, v1.y * inv1 + v2.y * inv2,
                        v1.z * inv1 + v2.z * inv2, v1.w * inv1 + v2.w * inv2);
    } else {
        int    r    = row - NW - NT;
        float  inv1 = inv_or_zero(g_deg[DEG_WD + r]);
        float  inv2 = inv_or_zero(g_deg[DEG_TD + r]);
        float4 v1   = *(const float4*)(g_s_wd + (size_t)r * DO + c);
        float4 v2   = *(const float4*)(g_s_td + (size_t)r * DO + c);
        o = make_float4(v1.x * inv1 + v2.x * inv2, v1.y * inv1 + v2.y * inv2,
                        v1.z * inv1 + v2.z * inv2, v1.w * inv1 + v2.w * inv2);
    }
    *(float4*)(out + (size_t)i * 4) = o;
}

// ---------------------------------------------------------------------------
// Host entry.
// Input order (metadata): 0 feat_word, 1 feat_topic,
//   2-4 ww(src,dst,w), 5-7 wt, 8-10 wd, 11-13 td, 14-16 tt,
//   17/18 W_ww/b_ww, 19/20 W_wt/b_wt, 21/22 W_wd/b_wd, 23/24 W_td/b_td,
//   25/26 W_tt/b_tt
// ---------------------------------------------------------------------------
extern "C" void kernel_launch(void* const* d_in, const int* in_sizes, int n_in,
                              void* d_out, int out_size) {
    const float* feat_word  = (const float*)d_in[0];
    const float* feat_topic = (const float*)d_in[1];

    const int*   e_src[5] = { (const int*)d_in[2],  (const int*)d_in[5],
                              (const int*)d_in[14], (const int*)d_in[8],
                              (const int*)d_in[11] };
    const int*   e_dst[5] = { (const int*)d_in[3],  (const int*)d_in[6],
                              (const int*)d_in[15], (const int*)d_in[9],
                              (const int*)d_in[12] };
    const float* e_w[5]   = { (const float*)d_in[4],  (const float*)d_in[7],
                              (const float*)d_in[16], (const float*)d_in[10],
                              (const float*)d_in[13] };
    const int    e_n[5]   = { in_sizes[2], in_sizes[5], in_sizes[14],
                              in_sizes[8], in_sizes[11] };

    const float* W_ww = (const float*)d_in[17]; const float* b_ww = (const float*)d_in[18];
    const float* W_wt = (const float*)d_in[19]; const float* b_wt = (const float*)d_in[20];
    const float* W_wd = (const float*)d_in[21]; const float* b_wd = (const float*)d_in[22];
    const float* W_td = (const float*)d_in[23]; const float* b_td = (const float*)d_in[24];
    const float* W_tt = (const float*)d_in[25]; const float* b_tt = (const float*)d_in[26];

    float* out = (float*)d_out;

    // 1. Zero accumulators + degrees.
    {
        const size_t maxe = (size_t)NW * DO;  // largest array span (6.4M)
        int blocks = (int)((maxe + 255) / 256);
        zero_all<<<blocks, 256>>>();
    }

    // 2. Per-relation projections. rel: 0=ww, 1=wt, 2=tt, 3=wd, 4=td.
    {
        int gw = (NW + 63) / 64;  // word-source GEMMs
        gemm_bias_k<256><<<gw, 256>>>(feat_word, W_ww, b_ww, 0, NW);
        gemm_bias_k<256><<<gw, 256>>>(feat_word, W_wt, b_wt, 1, NW);
        gemm_bias_k<256><<<gw, 256>>>(feat_word, W_wd, b_wd, 3, NW);
        int gt = (NT + 63) / 64;  // topic-source GEMMs
        gemm_bias_k<128><<<gt, 256>>>(feat_topic, W_tt, b_tt, 2, NT);
        gemm_bias_k<128><<<gt, 256>>>(feat_topic, W_td, b_td, 4, NT);
    }

    // 3. Edge scatter per relation (warp per edge).
    for (int rel = 0; rel < 5; rel++) {
        int E = e_n[rel];
        int blocks = (E + 7) / 8;  // 8 warps / block
        scatter_rel<<<blocks, 256>>>(e_src[rel], e_dst[rel], e_w[rel], rel, E);
    }

    // 4. Combine means, cross-etype sum, write output.
    {
        constexpr int TOT4 = (NW + NT + ND) * (DO / 4);
        combine<<<(TOT4 + 255) / 256, 256>>>(out);
    }
}

// round 4
// speedup vs baseline: 1.0889x; 1.0889x over previous
#include <cuda_runtime.h>
#include <cstdint>

// Problem dimensions (fixed by the reference).
#define NW 50000
#define NT 2000
#define ND 50000
#define DO 128

// Degree-array layout: one float counter per (relation, dst-node).
constexpr int DEG_WW = 0;
constexpr int DEG_WT = NW;
constexpr int DEG_TT = NW + NT;
constexpr int DEG_WD = NW + 2 * NT;
constexpr int DEG_TD = NW + 2 * NT + ND;
constexpr int NDEG   = NW + 2 * NT + 2 * ND;   // 154000

// ---------------------------------------------------------------------------
// Scratch (static __device__ arrays — allocation-free per harness rules).
// ---------------------------------------------------------------------------
__device__ float g_Wh_ww[(size_t)NW * DO];
__device__ float g_Wh_wt[(size_t)NW * DO];
__device__ float g_Wh_wd[(size_t)NW * DO];
__device__ float g_Wh_td[(size_t)NT * DO];
__device__ float g_Wh_tt[(size_t)NT * DO];

__device__ float g_s_ww[(size_t)NW * DO];
__device__ float g_s_wt[(size_t)NT * DO];
__device__ float g_s_tt[(size_t)NT * DO];
__device__ float g_s_wd[(size_t)ND * DO];
__device__ float g_s_td[(size_t)ND * DO];

__device__ float g_deg[NDEG];

// rel ids: 0=ww, 1=wt, 2=tt, 3=wd, 4=td
__device__ __forceinline__ float* wh_ptr(int rel) {
    switch (rel) {
        case 0:  return g_Wh_ww;
        case 1:  return g_Wh_wt;
        case 2:  return g_Wh_tt;
        case 3:  return g_Wh_wd;
        default: return g_Wh_td;
    }
}
__device__ __forceinline__ float* s_ptr(int rel) {
    switch (rel) {
        case 0:  return g_s_ww;
        case 1:  return g_s_wt;
        case 2:  return g_s_tt;
        case 3:  return g_s_wd;
        default: return g_s_td;
    }
}
__device__ __forceinline__ int deg_off(int rel) {
    switch (rel) {
        case 0:  return DEG_WW;
        case 1:  return DEG_WT;
        case 2:  return DEG_TT;
        case 3:  return DEG_WD;
        default: return DEG_TD;
    }
}

// ---------------------------------------------------------------------------
// Zero accumulators + degrees.
// ---------------------------------------------------------------------------
__global__ void zero_all() {
    size_t i = (size_t)blockIdx.x * blockDim.x + threadIdx.x;
    if (i < (size_t)NW * DO) g_s_ww[i] = 0.0f;
    if (i < (size_t)NT * DO) { g_s_wt[i] = 0.0f; g_s_tt[i] = 0.0f; }
    if (i < (size_t)ND * DO) { g_s_wd[i] = 0.0f; g_s_td[i] = 0.0f; }
    if (i < (size_t)NDEG)    g_deg[i] = 0.0f;
}

// ---------------------------------------------------------------------------
// Packed-f32x2 GEMM + bias: C[M x 128] = A[M x DIN] @ W[DIN x 128] + b
// BM=128, BN=128, BK=32, 256 threads, 8x8 microtile.
// Accumulators are 64-bit f32x2 pairs along N; fma.rn.f32x2 does 2 MACs/lane
// per instruction at the same fma-pipe rate as scalar FFMA (rt_SMSP=2),
// doubling the FFMA roofline. As is stored k-major (transposed) so the 8-row
// a-fragment loads as two contiguous LDS.128; b-fragments are natural 64-bit
// pairs. Only a-replication (mov.b64 {a,a}) is extra, on the alu pipe.
// ---------------------------------------------------------------------------
template <int DIN>
__global__ __launch_bounds__(256)
void gemm_bias_x2(const float* __restrict__ A, const float* __restrict__ W,
                  const float* __restrict__ bias, int rel, int M) {
    constexpr int BM = 128, BN = 128, BK = 32;
    __shared__ float As[BK][BM];   // transposed: [k][m]
    __shared__ float Bs[BK][BN];   // [k][n]

    const int t    = threadIdx.x;
    const int m0   = blockIdx.x * BM;
    const int lane = t & 31;
    const int tr   = t >> 4;        // 0..15
    const int tc   = t & 15;        // 0..15
    const int row0 = tr * 8;
    const int col0 = tc * 8;

    unsigned long long acc[8][4];
#pragma unroll
    for (int r = 0; r < 8; r++)
#pragma unroll
        for (int c = 0; c < 4; c++) acc[r][c] = 0ULL;

    for (int k0 = 0; k0 < DIN; k0 += BK) {
        // ---- Load A tile (128 rows x 32 k) transposed into As[k][m]. ----
        {
            int ar = t >> 1;          // 0..127 (row within tile)
            int ak = (t & 1) * 16;    // 0 or 16 (k offset)
            float v[16];
            if (m0 + ar < M) {
                const float* src = A + (size_t)(m0 + ar) * DIN + k0 + ak;
#pragma unroll
                for (int i = 0; i < 4; i++)
                    *(float4*)&v[i * 4] = *(const float4*)(src + i * 4);
            } else {
#pragma unroll
                for (int i = 0; i < 16; i++) v[i] = 0.0f;
            }
#pragma unroll
            for (int i = 0; i < 16; i++) As[ak + i][ar] = v[i];
        }
        // ---- Load B tile (32 k x 128 n). ----
        {
            int rb = t >> 5;  // 0..7
#pragma unroll
            for (int i = 0; i < 4; i++) {
                int r = rb + i * 8;
                *(float4*)&Bs[r][lane * 4] =
                    *(const float4*)(W + (size_t)(k0 + r) * BN + lane * 4);
            }
        }
        __syncthreads();

#pragma unroll
        for (int k = 0; k < BK; k++) {
            float a[8];
            *(float4*)(a)     = *(const float4*)&As[k][row0];
            *(float4*)(a + 4) = *(const float4*)&As[k][row0 + 4];
            unsigned long long b[4];
            *(ulonglong2*)(b)     = *(const ulonglong2*)&Bs[k][col0];
            *(ulonglong2*)(b + 2) = *(const ulonglong2*)&Bs[k][col0 + 4];
#pragma unroll
            for (int r = 0; r < 8; r++) {
                unsigned long long ap;
                asm("mov.b64 %0, {%1, %1};" : "=l"(ap) : "f"(a[r]));
#pragma unroll
                for (int c = 0; c < 4; c++)
                    asm("fma.rn.f32x2 %0, %1, %2, %0;"
                        : "+l"(acc[r][c]) : "l"(ap), "l"(b[c]));
            }
        }
        __syncthreads();
    }

    // ---- Epilogue: unpack, add bias, store. ----
    float* C = wh_ptr(rel);
    float bv[8];
    *(float4*)(bv)     = *(const float4*)(bias + col0);
    *(float4*)(bv + 4) = *(const float4*)(bias + col0 + 4);
#pragma unroll
    for (int r = 0; r < 8; r++) {
        int m = m0 + row0 + r;
        if (m < M) {
            float o[8];
#pragma unroll
            for (int c = 0; c < 4; c++)
                asm("mov.b64 {%0, %1}, %2;"
                    : "=f"(o[2 * c]), "=f"(o[2 * c + 1]) : "l"(acc[r][c]));
#pragma unroll
            for (int j = 0; j < 8; j++) o[j] += bv[j];
            float* dst = C + (size_t)m * BN + col0;
            *(float4*)(dst)     = *(float4*)(o);
            *(float4*)(dst + 4) = *(float4*)(o + 4);
        }
    }
}

// ---------------------------------------------------------------------------
// Edge scatter: one warp per edge. Each lane handles one float4 of the 128-wide
// row. Vector reduction red.global.add.v4.f32 cuts atomic instruction count 4x
// vs scalar atomicAdd. Lane 0 bumps the degree counter.
// ---------------------------------------------------------------------------
__global__ __launch_bounds__(256)
void scatter_rel(const int* __restrict__ src, const int* __restrict__ dst,
                 const float* __restrict__ w, int rel, int E) {
    int gw   = (int)(((size_t)blockIdx.x * blockDim.x + threadIdx.x) >> 5);
    int lane = threadIdx.x & 31;
    if (gw >= E) return;

    int   sN = src[gw];
    int   dN = dst[gw];
    float ew = w[gw];

    const float* Wh = wh_ptr(rel);
    float*       S  = s_ptr(rel);

    float4 v = *(const float4*)(Wh + (size_t)sN * DO + lane * 4);
    v.x *= ew; v.y *= ew; v.z *= ew; v.w *= ew;

    float* p = S + (size_t)dN * DO + lane * 4;
    asm volatile("red.global.add.v4.f32 [%0], {%1, %2, %3, %4};"
                 :: "l"(p), "f"(v.x), "f"(v.y), "f"(v.z), "f"(v.w)
                 : "memory");

    if (lane == 0) atomicAdd(g_deg + deg_off(rel) + dN, 1.0f);
}

// ---------------------------------------------------------------------------
// Combine: per-destination mean, cross-etype sum, write output
// [h_word(50000x128) | h_topic(2000x128) | h_doc(50000x128)].
// ---------------------------------------------------------------------------
__device__ __forceinline__ float inv_or_zero(float d) {
    return d > 0.0f ? 1.0f / d : 0.0f;
}

__global__ __launch_bounds__(256)
void combine(float* __restrict__ out) {
    constexpr int ROWS = NW + NT + ND;          // 102000
    constexpr int TOT4 = ROWS * (DO / 4);       // float4 elements
    int i = (int)((size_t)blockIdx.x * blockDim.x + threadIdx.x);
    if (i >= TOT4) return;

    int row = i >> 5;           // DO/4 = 32 float4 per row
    int c   = (i & 31) * 4;     // float offset within row

    float4 o;
    if (row < NW) {
        float  inv = inv_or_zero(g_deg[DEG_WW + row]);
        float4 v   = *(const float4*)(g_s_ww + (size_t)row * DO + c);
        o = make_float4(v.x * inv, v.y * inv, v.z * inv, v.w * inv);
    } else if (row < NW + NT) {
        int    r    = row - NW;
        float  inv1 = inv_or_zero(g_deg[DEG_WT + r]);
        float  inv2 = inv_or_zero(g_deg[DEG_TT + r]);
        float4 v1   = *(const float4*)(g_s_wt + (size_t)r * DO + c);
        float4 v2   = *(const float4*)(g_s_tt + (size_t)r * DO + c);
        o = make_float4(v1.x * inv1 + v2.x * inv2, v1.y * inv1 + v2.y * inv2,
                        v1.z * inv1 + v2.z * inv2, v1.w * inv1 + v2.w * inv2);
    } else {
        int    r    = row - NW - NT;
        float  inv1 = inv_or_zero(g_deg[DEG_WD + r]);
        float  inv2 = inv_or_zero(g_deg[DEG_TD + r]);
        float4 v1   = *(const float4*)(g_s_wd + (size_t)r * DO + c);
        float4 v2   = *(const float4*)(g_s_td + (size_t)r * DO + c);
        o = make_float4(v1.x * inv1 + v2.x * inv2, v1.y * inv1 + v2.y * inv2,
                        v1.z * inv1 + v2.z * inv2, v1.w * inv1 + v2.w * inv2);
    }
    *(float4*)(out + (size_t)i * 4) = o;
}

// ---------------------------------------------------------------------------
// Host entry.
// Input order (metadata): 0 feat_word, 1 feat_topic,
//   2-4 ww(src,dst,w), 5-7 wt, 8-10 wd, 11-13 td, 14-16 tt,
//   17/18 W_ww/b_ww, 19/20 W_wt/b_wt, 21/22 W_wd/b_wd, 23/24 W_td/b_td,
//   25/26 W_tt/b_tt
//
// Fork-join overlap: GEMMs (fma-bound) stay on the legacy stream; the L2-bound
// scatters run on a side stream gated per-relation by events, so scatter(rel)
// starts as soon as its own GEMM is done while the remaining GEMMs execute
// concurrently. combine joins both branches. All captured as one graph.
// ---------------------------------------------------------------------------
extern "C" void kernel_launch(void* const* d_in, const int* in_sizes, int n_in,
                              void* d_out, int out_size) {
    static cudaStream_t s2 = nullptr;
    static cudaEvent_t  evZ, evG[5], evS;
    if (s2 == nullptr) {
        cudaStreamCreateWithFlags(&s2, cudaStreamNonBlocking);
        cudaEventCreateWithFlags(&evZ, cudaEventDisableTiming);
        for (int i = 0; i < 5; i++)
            cudaEventCreateWithFlags(&evG[i], cudaEventDisableTiming);
        cudaEventCreateWithFlags(&evS, cudaEventDisableTiming);
    }

    const float* feat_word  = (const float*)d_in[0];
    const float* feat_topic = (const float*)d_in[1];

    const int*   e_src[5] = { (const int*)d_in[2],  (const int*)d_in[5],
                              (const int*)d_in[14], (const int*)d_in[8],
                              (const int*)d_in[11] };
    const int*   e_dst[5] = { (const int*)d_in[3],  (const int*)d_in[6],
                              (const int*)d_in[15], (const int*)d_in[9],
                              (const int*)d_in[12] };
    const float* e_w[5]   = { (const float*)d_in[4],  (const float*)d_in[7],
                              (const float*)d_in[16], (const float*)d_in[10],
                              (const float*)d_in[13] };
    const int    e_n[5]   = { in_sizes[2], in_sizes[5], in_sizes[14],
                              in_sizes[8], in_sizes[11] };

    const float* W_ww = (const float*)d_in[17]; const float* b_ww = (const float*)d_in[18];
    const float* W_wt = (const float*)d_in[19]; const float* b_wt = (const float*)d_in[20];
    const float* W_wd = (const float*)d_in[21]; const float* b_wd = (const float*)d_in[22];
    const float* W_td = (const float*)d_in[23]; const float* b_td = (const float*)d_in[24];
    const float* W_tt = (const float*)d_in[25]; const float* b_tt = (const float*)d_in[26];

    float* out = (float*)d_out;

    // 1. Zero accumulators + degrees (legacy stream).
    {
        const size_t maxe = (size_t)NW * DO;  // largest array span (6.4M)
        int blocks = (int)((maxe + 255) / 256);
        zero_all<<<blocks, 256>>>();
        cudaEventRecord(evZ, 0);
    }

    // 2. Projections on legacy stream, each followed by an event.
    //    rel ids: 0=ww, 1=wt, 2=tt, 3=wd, 4=td. Word GEMMs first (they gate
    //    the longest scatters).
    {
        int gw = (NW + 127) / 128;
        gemm_bias_x2<256><<<gw, 256>>>(feat_word, W_ww, b_ww, 0, NW);
        cudaEventRecord(evG[0], 0);
        gemm_bias_x2<256><<<gw, 256>>>(feat_word, W_wt, b_wt, 1, NW);
        cudaEventRecord(evG[1], 0);
        gemm_bias_x2<256><<<gw, 256>>>(feat_word, W_wd, b_wd, 3, NW);
        cudaEventRecord(evG[3], 0);
        int gt = (NT + 127) / 128;
        gemm_bias_x2<128><<<gt, 256>>>(feat_topic, W_td, b_td, 4, NT);
        cudaEventRecord(evG[4], 0);
        gemm_bias_x2<128><<<gt, 256>>>(feat_topic, W_tt, b_tt, 2, NT);
        cudaEventRecord(evG[2], 0);
    }

    // 3. Edge scatters on side stream, gated per relation.
    {
        cudaStreamWaitEvent(s2, evZ, 0);
        const int order[5] = {0, 1, 3, 4, 2};
        for (int i = 0; i < 5; i++) {
            int rel = order[i];
            cudaStreamWaitEvent(s2, evG[rel], 0);
            int E = e_n[rel];
            int blocks = (E + 7) / 8;  // 8 warps / block, warp per edge
            scatter_rel<<<blocks, 256, 0, s2>>>(e_src[rel], e_dst[rel],
                                                e_w[rel], rel, E);
        }
        cudaEventRecord(evS, s2);
    }

    // 4. Join and combine on legacy stream.
    {
        cudaStreamWaitEvent(0, evS, 0);
        constexpr int TOT4 = (NW + NT + ND) * (DO / 4);
        combine<<<(TOT4 + 255) / 256, 256>>>(out);
    }
}